// round 15
// baseline (speedup 1.0000x reference)
#include <cuda_runtime.h>
#include <math.h>

// Sinkhorn approximate EMD: B=8, N=2048, 3D points, 50 iterations.
// R15: one 2-CTA cluster per batch (16 CTAs x 1024 thr, 1024 rows/CTA).
// Exchange vectors live in smem; row leaders write new exp values locally
// AND to the single peer via st.shared::cluster; the only sync is
// barrier.cluster (~0.35us) - no gpu-scope barrier, no L2 staging.
// Packed ELL (cutoff K>=1e-17), multiplicative updates, LDS gathers,
// deterministic reductions throughout.

#define BB 8
#define NN 2048
#define RSTRIDE 256              // padded max nnz per row (avg ~45, max ~190)
#define D2CUT 0.391510f          // ln(1e17)/100  -> K >= 1e-17
#define TPB 1024
#define RPC 1024                 // rows per CTA per matrix
#define NCTA 16

__device__ unsigned g_pk[(size_t)NCTA * 2 * RPC * RSTRIDE];   // K|KT slices (33.5 MB)
__device__ float    g_part[NCTA];

__device__ __forceinline__ unsigned smem_u32(const void* p) {
    unsigned a;
    asm("{ .reg .u64 t; cvta.to.shared.u64 t, %1; cvt.u32.u64 %0, t; }"
        : "=r"(a) : "l"(p));
    return a;
}
__device__ __forceinline__ unsigned mapa_sm(unsigned addr, unsigned rank) {
    unsigned r;
    asm("mapa.shared::cluster.u32 %0, %1, %2;" : "=r"(r) : "r"(addr), "r"(rank));
    return r;
}
__device__ __forceinline__ void st_cluster(unsigned addr, float v) {
    asm volatile("st.shared::cluster.f32 [%0], %1;" :: "r"(addr), "f"(v) : "memory");
}
#define CLUSTER_SYNC() do {                                              \
    asm volatile("barrier.cluster.arrive.aligned;" ::: "memory");        \
    asm volatile("barrier.cluster.wait.aligned;"   ::: "memory");        \
} while (0)

__device__ __forceinline__ float dot4(uint4 e, const float* sev) {
    return __uint_as_float(e.x & 0xFFFFF800u) * sev[e.x & 0x7FFu]
         + __uint_as_float(e.y & 0xFFFFF800u) * sev[e.y & 0x7FFu]
         + __uint_as_float(e.z & 0xFFFFF800u) * sev[e.z & 0x7FFu]
         + __uint_as_float(e.w & 0xFFFFF800u) * sev[e.w & 0x7FFu];
}

// ---------------------------------------------------------------------------
__global__ __cluster_dims__(2, 1, 1) __launch_bounds__(TPB, 1)
void fused_sinkhorn(const float* __restrict__ x1, const float* __restrict__ x2,
                    float* __restrict__ out, float M) {
    __shared__ __align__(16) float pool[NN * 3];   // build staging; then su | sv
    __shared__ unsigned char sit[2][RPC];          // per-row 16-entry iter counts
    __shared__ float red[32];
    float* su = pool;          // exp(u)[0..2047]  (full batch, both CTAs mirror)
    float* sv = pool + NN;     // exp(v)[0..2047]

    int cta = blockIdx.x, batch = cta >> 1;
    unsigned crank = (unsigned)(cta & 1);
    int t = threadIdx.x, warp = t >> 5, lane = t & 31;
    int rb = (int)crank * RPC;                     // this CTA's row offset in batch
    const float eps = 1e-8f;

    // ===== build: this CTA's 1024 rows of K (m=0) and K^T (m=1) =====
    #pragma unroll 1
    for (int m = 0; m < 2; ++m) {
        const float* rowpts = m ? x2 : x1;
        const float* colpts = m ? x1 : x2;
        const float* cp = colpts + (size_t)batch * NN * 3;
        for (int i = t; i < NN * 3; i += TPB) pool[i] = cp[i];
        __syncthreads();

        #pragma unroll 1
        for (int rr = 0; rr < RPC / 32; ++rr) {    // 32 rows per warp
            int r = warp * (RPC / 32) + rr;
            const float* ap = rowpts + ((size_t)batch * NN + rb + r) * 3;
            float ax = ap[0], ay = ap[1], az = ap[2];
            unsigned* krow = g_pk + ((size_t)(cta * 2 + m) * RPC + r) * RSTRIDE;

            unsigned base = 0;
            for (int c0 = 0; c0 < NN; c0 += 32) {
                int c = c0 + lane;
                float dx = ax - pool[3 * c];
                float dy = ay - pool[3 * c + 1];
                float dz = az - pool[3 * c + 2];
                float d2 = fmaf(dx, dx, fmaf(dy, dy, dz * dz));
                bool p = d2 < D2CUT;
                unsigned mk = __ballot_sync(0xffffffffu, p);
                if (p) {
                    unsigned idx = base + __popc(mk & ((1u << lane) - 1u));
                    if (idx < RSTRIDE)   // RN-rounded 21-bit val | 11-bit col
                        krow[idx] = ((__float_as_uint(__expf(-100.0f * d2)) + 0x400u)
                                     & 0xFFFFF800u) | (unsigned)c;
                }
                base += __popc(mk);
            }
            unsigned nnz = (base < RSTRIDE) ? base : RSTRIDE;
            unsigned pad = (nnz + 15u) & ~15u;     // 16 entries per group-iter
            for (unsigned idx = nnz + lane; idx < pad; idx += 32) krow[idx] = 0u;
            if (lane == 0) sit[m][r] = (unsigned char)(pad >> 4);
        }
        __syncthreads();
    }

    // init sv = exp(v0) = 1 across the FULL batch (local copy; peer does its own)
    if (t < NN / 4) ((float4*)sv)[t] = make_float4(1.f, 1.f, 1.f, 1.f);
    __syncthreads();

    // peer smem addresses (computed once)
    unsigned su_rem = mapa_sm(smem_u32(su), crank ^ 1u);
    unsigned sv_rem = mapa_sm(smem_u32(sv), crank ^ 1u);

    // ===== 100 Sinkhorn half-iterations; only sync = barrier.cluster =====
    int g = t >> 2, gl = t & 3;                    // 256 groups x 4 lanes
    #pragma unroll 1
    for (int half = 0; half < 100; ++half) {
        int m = half & 1;   // 0: u update (K, reads sv, writes su); 1: v update
        const float* src = m ? su : sv;
        float*   dstl = m ? sv : su;
        unsigned dstr = m ? sv_rem : su_rem;

        #pragma unroll 1
        for (int rr = 0; rr < 4; ++rr) {           // 4 rows per group
            int r = g + rr * 256;
            int iters = sit[m][r];
            const uint4* ep =
                (const uint4*)(g_pk + ((size_t)(cta * 2 + m) * RPC + r) * RSTRIDE) + gl;
            float acc = 0.0f;
            #pragma unroll 2
            for (int i = 0; i < iters; ++i)
                acc += dot4(ep[(size_t)i * 4], src);
            acc += __shfl_xor_sync(0xffffffffu, acc, 2);
            acc += __shfl_xor_sync(0xffffffffu, acc, 1);
            if (gl == 0) {    // multiplicative update: exp(new) = M / (sum + eps)
                float ev = __fdividef(M, acc + eps);
                int idx = rb + r;
                dstl[idx] = ev;                          // own copy
                st_cluster(dstr + (unsigned)idx * 4u, ev);   // peer copy
            }
        }
        CLUSTER_SYNC();   // release own (local+remote) stores; acquire peer's
    }

    // ===== epilogue: both su (exp u) and sv (exp v) are complete locally =====
    float acc = 0.0f;
    #pragma unroll 1
    for (int rr = 0; rr < 4; ++rr) {
        int r = g + rr * 256;
        int iters = sit[0][r];
        const uint4* ep =
            (const uint4*)(g_pk + ((size_t)(cta * 2 + 0) * RPC + r) * RSTRIDE) + gl;
        float racc = 0.0f;
        #pragma unroll 1
        for (int i = 0; i < iters; ++i) {
            uint4 e = ep[(size_t)i * 4];
            unsigned b;
            b = e.x & 0xFFFFF800u;
            if (b) { float k = __uint_as_float(b); racc += k * __logf(k) * sv[e.x & 0x7FFu]; }
            b = e.y & 0xFFFFF800u;
            if (b) { float k = __uint_as_float(b); racc += k * __logf(k) * sv[e.y & 0x7FFu]; }
            b = e.z & 0xFFFFF800u;
            if (b) { float k = __uint_as_float(b); racc += k * __logf(k) * sv[e.z & 0x7FFu]; }
            b = e.w & 0xFFFFF800u;
            if (b) { float k = __uint_as_float(b); racc += k * __logf(k) * sv[e.w & 0x7FFu]; }
        }
        racc += __shfl_xor_sync(0xffffffffu, racc, 2);
        racc += __shfl_xor_sync(0xffffffffu, racc, 1);
        if (gl == 0) acc += racc * su[rb + r];     // row weight exp(u_i)
    }
    // fixed-order block reduce (leaders carry, others 0)
    #pragma unroll
    for (int o = 16; o; o >>= 1) acc += __shfl_down_sync(0xffffffffu, acc, o);
    if (lane == 0) red[warp] = acc;
    __syncthreads();
    if (warp == 0) {
        float s = red[lane];
        #pragma unroll
        for (int o = 16; o; o >>= 1) s += __shfl_down_sync(0xffffffffu, s, o);
        if (lane == 0) __stcg(&g_part[cta], s);
    }
    CLUSTER_SYNC();   // cluster-scope release/acquire covers the global partials

    if (crank == 0 && t == 0) {
        float s = __ldcg(&g_part[cta]) + __ldcg(&g_part[cta + 1]);
        out[batch] = -s * 0.01f;                   // cost = -ln(K)/100
    }
}

// ---------------------------------------------------------------------------
extern "C" void kernel_launch(void* const* d_in, const int* in_sizes, int n_in,
                              void* d_out, int out_size) {
    (void)in_sizes; (void)n_in; (void)out_size;
    const float* x1 = (const float*)d_in[0];
    const float* x2 = (const float*)d_in[1];
    float* out = (float*)d_out;

    const float M = 1.0f / 2048.0f + 1e-8f;   // exp(log(1/N + eps_log))
    fused_sinkhorn<<<NCTA, TPB>>>(x1, x2, out, M);
}

// round 16
// speedup vs baseline: 2.7759x; 2.7759x over previous
#include <cuda_runtime.h>
#include <math.h>

// Sinkhorn approximate EMD: B=8, N=2048, 3D points, 50 iterations.
// R16: one 8-CTA cluster per batch (64 CTAs x 1024 thr, 256 rows/CTA).
// Exchange through L2 (leaders stcg, peers ldcg-stage after sync); the only
// sync is barrier.cluster (HW, ~0.3-0.5us) - no gpu-scope software barrier.
// Gathers via smem (LDS) per R12 lesson; prefetch across the sync per R11;
// packed ELL cutoff K>=1e-17; multiplicative updates; deterministic sums.

#define BB 8
#define NN 2048
#define RSTRIDE 256              // padded max nnz per row (avg ~41, max ~150)
#define D2CUT 0.391510f          // ln(1e17)/100  -> K >= 1e-17
#define CL 8                     // CTAs per cluster = per batch
#define RPC 256                  // rows per CTA
#define TPB 1024                 // 256 groups x 4 lanes
#define NCTA 64

__device__ unsigned g_pk[(size_t)NCTA * 2 * RPC * RSTRIDE];  // K|KT slices (33.5 MB)
__device__ float    g_expu[BB * NN], g_expv[BB * NN];
__device__ float    g_part[NCTA];

#define CLUSTER_ARRIVE() asm volatile("barrier.cluster.arrive.aligned;" ::: "memory")
#define CLUSTER_WAIT()   asm volatile("barrier.cluster.wait.aligned;"   ::: "memory")

__device__ __forceinline__ float dot4(uint4 e, const float* sev) {
    return __uint_as_float(e.x & 0xFFFFF800u) * sev[e.x & 0x7FFu]
         + __uint_as_float(e.y & 0xFFFFF800u) * sev[e.y & 0x7FFu]
         + __uint_as_float(e.z & 0xFFFFF800u) * sev[e.z & 0x7FFu]
         + __uint_as_float(e.w & 0xFFFFF800u) * sev[e.w & 0x7FFu];
}

// ---------------------------------------------------------------------------
__global__ __cluster_dims__(CL, 1, 1) __launch_bounds__(TPB, 1)
void fused_sinkhorn(const float* __restrict__ x1, const float* __restrict__ x2,
                    float* __restrict__ out, float M) {
    __shared__ __align__(16) float pool[NN * 3];   // build pts; first 2048 = sev
    __shared__ unsigned char sit[2][RPC];          // per-row 16-entry iter counts
    __shared__ float red[32];
    float* sev = pool;

    int cta = blockIdx.x, batch = cta >> 3, crank = cta & (CL - 1);
    int t = threadIdx.x, warp = t >> 5, lane = t & 31;
    int rowbase = batch * NN + crank * RPC;
    const float eps = 1e-8f;

    // ===== build: CTA-private packed-ELL rows of K (m=0) and K^T (m=1) =====
    #pragma unroll 1
    for (int m = 0; m < 2; ++m) {
        const float* rowpts = m ? x2 : x1;
        const float* colpts = m ? x1 : x2;
        const float* cp = colpts + (size_t)batch * NN * 3;
        for (int i = t; i < NN * 3; i += TPB) pool[i] = cp[i];
        __syncthreads();

        #pragma unroll 1
        for (int rr = 0; rr < RPC / 32; ++rr) {    // 8 rows per warp
            int r = warp * (RPC / 32) + rr;
            const float* ap = rowpts + ((size_t)rowbase + r) * 3;
            float ax = ap[0], ay = ap[1], az = ap[2];
            unsigned* krow = g_pk + ((size_t)(cta * 2 + m) * RPC + r) * RSTRIDE;

            unsigned base = 0;
            for (int c0 = 0; c0 < NN; c0 += 32) {
                int c = c0 + lane;
                float dx = ax - pool[3 * c];
                float dy = ay - pool[3 * c + 1];
                float dz = az - pool[3 * c + 2];
                float d2 = fmaf(dx, dx, fmaf(dy, dy, dz * dz));
                bool p = d2 < D2CUT;
                unsigned mk = __ballot_sync(0xffffffffu, p);
                if (p) {
                    unsigned idx = base + __popc(mk & ((1u << lane) - 1u));
                    if (idx < RSTRIDE)   // RN-rounded 21-bit val | 11-bit col
                        krow[idx] = ((__float_as_uint(__expf(-100.0f * d2)) + 0x400u)
                                     & 0xFFFFF800u) | (unsigned)c;
                }
                base += __popc(mk);
            }
            unsigned nnz = (base < RSTRIDE) ? base : RSTRIDE;
            unsigned pad = (nnz + 15u) & ~15u;     // 16 entries per group-iter
            if (pad == 0) pad = 16;
            for (unsigned idx = nnz + lane; idx < pad; idx += 32) krow[idx] = 0u;
            if (lane == 0) sit[m][r] = (unsigned char)(pad >> 4);
        }
        __syncthreads();
    }

    // ===== 100 Sinkhorn half-iterations; only sync = barrier.cluster =====
    int g = t >> 2, gl = t & 3;                    // 256 groups x 4 lanes
    int myrow = rowbase + g;                       // each group owns one row
    int itc0 = sit[0][g], itc1 = sit[1][g];
    const uint4* ep0 = (const uint4*)(g_pk + ((size_t)(cta * 2 + 0) * RPC + g) * RSTRIDE) + gl;
    const uint4* ep1 = (const uint4*)(g_pk + ((size_t)(cta * 2 + 1) * RPC + g) * RSTRIDE) + gl;
    float myeu = 0.0f;                             // leader: final exp(u)

    // half 0 input: exp(v0) = 1
    if (t < NN / 4) ((float4*)sev)[t] = make_float4(1.f, 1.f, 1.f, 1.f);

    // prefetch half 0's first 48 entries (in-bounds: RSTRIDE/4 = 64 uint4/lane)
    uint4 f0 = ep0[0];
    uint4 f1 = ep0[4];
    uint4 f2 = ep0[8];

    #pragma unroll 1
    for (int half = 0; half < 100; ++half) {
        int m = half & 1;   // 0: u update (K, reads expv); 1: v update (K^T, reads expu)

        if (half > 0 && t < NN / 4)   // stage exchange vector from L2
            ((float4*)sev)[t] =
                __ldcg((const float4*)((m ? g_expu : g_expv) + batch * NN) + t);
        __syncthreads();

        int iters = m ? itc1 : itc0;
        const uint4* ep = m ? ep1 : ep0;

        float acc = dot4(f0, sev);                 // prefetched chunks
        if (iters > 1) acc += dot4(f1, sev);
        if (iters > 2) acc += dot4(f2, sev);
        #pragma unroll 1
        for (int i = 3; i < iters; ++i)            // rare tail (nnz > 48)
            acc += dot4(ep[(size_t)i * 4], sev);

        acc += __shfl_xor_sync(0xffffffffu, acc, 2);
        acc += __shfl_xor_sync(0xffffffffu, acc, 1);

        if (gl == 0) {       // multiplicative update: exp(new) = M / (sum + eps)
            float ev = __fdividef(M, acc + eps);
            if (m == 0) myeu = ev;                 // half 98 leaves final exp(u)
            __stcg((m ? g_expv : g_expu) + myrow, ev);
        }

        // prefetch NEXT half's first 48 entries (overlaps the cluster barrier)
        {
            const uint4* nep = m ? ep0 : ep1;
            f0 = nep[0];
            f1 = nep[4];
            f2 = nep[8];
        }

        // release own stores; acquire peers' (cluster scope covers global mem);
        // wait also acts as an intra-CTA barrier before the next stage.
        CLUSTER_ARRIVE();
        CLUSTER_WAIT();
    }

    // ===== epilogue: emd_b = -(1/100) sum_ij k ln(k) e^{u_i} e^{v_j} =====
    if (t < NN / 4)
        ((float4*)sev)[t] = __ldcg((const float4*)(g_expv + batch * NN) + t);
    __syncthreads();

    float racc = 0.0f;
    #pragma unroll 1
    for (int i = 0; i < itc0; ++i) {
        uint4 e = ep0[(size_t)i * 4];
        unsigned b;
        b = e.x & 0xFFFFF800u;
        if (b) { float k = __uint_as_float(b); racc += k * __logf(k) * sev[e.x & 0x7FFu]; }
        b = e.y & 0xFFFFF800u;
        if (b) { float k = __uint_as_float(b); racc += k * __logf(k) * sev[e.y & 0x7FFu]; }
        b = e.z & 0xFFFFF800u;
        if (b) { float k = __uint_as_float(b); racc += k * __logf(k) * sev[e.z & 0x7FFu]; }
        b = e.w & 0xFFFFF800u;
        if (b) { float k = __uint_as_float(b); racc += k * __logf(k) * sev[e.w & 0x7FFu]; }
    }
    racc += __shfl_xor_sync(0xffffffffu, racc, 2);
    racc += __shfl_xor_sync(0xffffffffu, racc, 1);

    float acc = (gl == 0) ? racc * myeu : 0.0f;    // leaders carry row sums
    #pragma unroll
    for (int o = 16; o; o >>= 1) acc += __shfl_down_sync(0xffffffffu, acc, o);
    if (lane == 0) red[warp] = acc;
    __syncthreads();
    if (warp == 0) {
        float s = red[lane];
        #pragma unroll
        for (int o = 16; o; o >>= 1) s += __shfl_down_sync(0xffffffffu, s, o);
        if (lane == 0) __stcg(&g_part[cta], s);
    }

    // cluster barrier: releases the g_part stores, then rank 0 reduces
    CLUSTER_ARRIVE();
    CLUSTER_WAIT();

    if (crank == 0 && t == 0) {
        float s = 0.0f;
        #pragma unroll
        for (int k = 0; k < CL; ++k) s += __ldcg(&g_part[(cta & ~(CL - 1)) + k]);
        out[batch] = -s * 0.01f;                   // cost = -ln(K)/100
    }
}

// ---------------------------------------------------------------------------
extern "C" void kernel_launch(void* const* d_in, const int* in_sizes, int n_in,
                              void* d_out, int out_size) {
    (void)in_sizes; (void)n_in; (void)out_size;
    const float* x1 = (const float*)d_in[0];
    const float* x2 = (const float*)d_in[1];
    float* out = (float*)d_out;

    const float M = 1.0f / 2048.0f + 1e-8f;   // exp(log(1/N + eps_log))
    fused_sinkhorn<<<NCTA, TPB>>>(x1, x2, out, M);
}